// round 6
// baseline (speedup 1.0000x reference)
#include <cuda_runtime.h>
#include <cstdint>

// ---------------------------------------------------------------------------
// HDCTokenEncoder: out[b,i,d] = item_memory[tok[b,i]][(d - i) mod D] * (1/sqrt(D))
// item_memory entries are exactly +/-1 => row L2 norm == sqrt(D) == 100 exactly,
// so normalization is the constant 0.01f (applied once while staging SMEM).
//
// R6 design: block (t, y) handles positions { i : i % 16 == y } of token t;
// all share m = r mod 4 = y & 3. Stage the PRE-ROTATED row
//   T[d] = 0.01 * row[(d - m) mod D]
// once, so each output row is T rotated by whole float4 quads (q0 = (r-m)/4).
// Emission processes rows in GROUPS of up to 4 with quads as the outer loop:
// one LDS.128 feeds up to 4 STG.128 (register reuse) -> smem-read traffic per
// output quad drops ~4x vs R5; the mandatory 655MB DRAM write stream binds.
// ---------------------------------------------------------------------------

#define HDC_D      10000
#define HDC_D4     2500              // D / 4
#define HDC_ROWB   40000u            // row bytes
#define HDC_S      2048              // sequence length (power of two)
#define HDC_BS     16384             // B * S
#define HDC_V      256
#define PSPLIT     16                // position classes (multiple of 4)
#define CAND       (HDC_BS / PSPLIT) // 1024 candidates per block
#define NTHR       512

template <int OFS>
__device__ __forceinline__ float4 blend(float4 A, float4 B) {
    if (OFS == 0) return A;
    if (OFS == 1) return make_float4(A.y, A.z, A.w, B.x);
    if (OFS == 2) return make_float4(A.z, A.w, B.x, B.y);
    return make_float4(A.w, B.x, B.y, B.z);
}

// Stage T[d] = 0.01 * s[(d - m) mod D]; OFS = (-m) mod 4.
template <int OFS>
__device__ __forceinline__ void stage(const float4* __restrict__ sq,
                                      float4* __restrict__ T4, int m) {
    const float scale = 0.01f;
    for (int g = threadIdx.x; g < HDC_D4; g += NTHR) {
        int s0 = 4 * g - m;
        if (s0 < 0) s0 += HDC_D;
        int qa = s0 >> 2;
        float4 v;
        if (OFS == 0) {
            v = __ldg(&sq[qa]);
        } else {
            int qb = qa + 1;
            if (qb == HDC_D4) qb = 0;
            v = blend<OFS>(__ldg(&sq[qa]), __ldg(&sq[qb]));
        }
        v.x *= scale; v.y *= scale; v.z *= scale; v.w *= scale;
        T4[g] = v;
    }
}

// Emit K rows at once: quads outer, one LDS.128 shared by K STG.128.
template <int K>
__device__ __forceinline__ void emit_group(const float4* __restrict__ T4,
                                           char* __restrict__ outb,
                                           const int* __restrict__ list,
                                           int p0, int m) {
    uint32_t off[K];
    int      q0[K];
    #pragma unroll
    for (int k = 0; k < K; ++k) {
        int bs  = list[p0 + k];
        int r   = bs & (HDC_S - 1);          // r mod 4 == m by construction
        q0[k]   = (r - m) >> 2;              // whole-quad rotation, in [0, 512)
        off[k]  = (uint32_t)bs * HDC_ROWB;   // fits 32 bits (655MB total)
    }
    for (int g = threadIdx.x; g < HDC_D4; g += NTHR) {
        float4 v = T4[g];                    // single smem read
        #pragma unroll
        for (int k = 0; k < K; ++k) {
            int go = g + q0[k];
            if (go >= HDC_D4) go -= HDC_D4;
            __stcs(reinterpret_cast<float4*>(outb + off[k] + ((uint32_t)go << 4)), v);
        }
    }
}

__global__ __launch_bounds__(NTHR) void k_encode(const int* __restrict__ tok,
                                                 const float* __restrict__ im,
                                                 float* __restrict__ out) {
    __shared__ float4 T4[HDC_D4];      // 40 KB pre-rotated, pre-scaled row
    __shared__ int    list[CAND];      // matching flat positions
    __shared__ int    nmatch;

    const int t = blockIdx.x;          // token id
    const int y = blockIdx.y;          // position class: i % 16 == y
    const int m = y & 3;               // shared r mod 4 for all rows here

    if (threadIdx.x == 0) nmatch = 0;
    __syncthreads();

    // Phase 1: find positions (candidate i = y + 16*j); token array is L2-hot.
    #pragma unroll
    for (int j = threadIdx.x; j < CAND; j += NTHR) {
        int i = y + PSPLIT * j;
        if (__ldg(&tok[i]) == t) {
            int k = atomicAdd(&nmatch, 1);
            list[k] = i;
        }
    }
    __syncthreads();

    const int n = nmatch;
    if (n == 0) return;

    // Phase 2: stage the pre-rotated, pre-scaled row (blend paid once).
    const float4* sq = reinterpret_cast<const float4*>(im + (size_t)t * HDC_D);
    switch ((4 - m) & 3) {
        case 0: stage<0>(sq, T4, m); break;
        case 1: stage<1>(sq, T4, m); break;
        case 2: stage<2>(sq, T4, m); break;
        default: stage<3>(sq, T4, m); break;
    }
    __syncthreads();

    // Phase 3: emit rows in groups of 4 (register-reused LDS).
    char* outb = reinterpret_cast<char*>(out);
    int p0 = 0;
    for (; p0 + 4 <= n; p0 += 4)
        emit_group<4>(T4, outb, list, p0, m);
    switch (n - p0) {
        case 1: emit_group<1>(T4, outb, list, p0, m); break;
        case 2: emit_group<2>(T4, outb, list, p0, m); break;
        case 3: emit_group<3>(T4, outb, list, p0, m); break;
        default: break;
    }
}

extern "C" void kernel_launch(void* const* d_in, const int* in_sizes, int n_in,
                              void* d_out, int out_size) {
    const int*   tok = (const int*)d_in[0];     // (B, S) int32
    const float* im  = (const float*)d_in[1];   // (V, D) float32
    float*       out = (float*)d_out;           // (B, S, D) float32
    (void)in_sizes; (void)n_in; (void)out_size;

    dim3 grid(HDC_V, PSPLIT);
    k_encode<<<grid, NTHR>>>(tok, im, out);
}

// round 7
// speedup vs baseline: 1.0042x; 1.0042x over previous
#include <cuda_runtime.h>
#include <cstdint>

// ---------------------------------------------------------------------------
// HDCTokenEncoder: out[b,i,d] = item_memory[tok[b,i]][(d - i) mod D] * (1/sqrt(D))
// item_memory entries are exactly +/-1 => row L2 norm == sqrt(D) == 100 exactly,
// so normalization is the constant 0.01f (applied once while staging SMEM).
//
// R7 = R5 emission (store-address 32B-sector alignment preserved: stores land
// at out quad g with warp-chunk starts multiple of 512B within a 32B-aligned
// row) + PSPLIT 16->8 so the per-block fixed cost (candidate scan + 40KB row
// staging) is amortized over ~8 output rows instead of ~4.
//
// Block (t, y): positions { i : i % 8 == y } of token t; all share
// m = r mod 4 = y & 3. Stage pre-rotated row T[d] = 0.01*row[(d-m) mod D]
// once; each output row is then a whole-quad rotation: load T[(g-q0) mod D4],
// store at quad g (aligned), q0 = (r-m)/4.
// ---------------------------------------------------------------------------

#define HDC_D      10000
#define HDC_D4     2500              // D / 4
#define HDC_S      2048              // sequence length (power of two)
#define HDC_BS     16384             // B * S
#define HDC_V      256
#define PSPLIT     8                 // position classes (multiple of 4)
#define CAND       (HDC_BS / PSPLIT) // 2048 candidates per block
#define NTHR       512

template <int OFS>
__device__ __forceinline__ float4 blend(float4 A, float4 B) {
    if (OFS == 0) return A;
    if (OFS == 1) return make_float4(A.y, A.z, A.w, B.x);
    if (OFS == 2) return make_float4(A.z, A.w, B.x, B.y);
    return make_float4(A.w, B.x, B.y, B.z);
}

// Stage T[d] = 0.01 * s[(d - m) mod D]; OFS = (-m) mod 4.
template <int OFS>
__device__ __forceinline__ void stage(const float4* __restrict__ sq,
                                      float4* __restrict__ T4, int m) {
    const float scale = 0.01f;
    for (int g = threadIdx.x; g < HDC_D4; g += NTHR) {
        int s0 = 4 * g - m;
        if (s0 < 0) s0 += HDC_D;
        int qa = s0 >> 2;
        float4 v;
        if (OFS == 0) {
            v = __ldg(&sq[qa]);
        } else {
            int qb = qa + 1;
            if (qb == HDC_D4) qb = 0;
            v = blend<OFS>(__ldg(&sq[qa]), __ldg(&sq[qb]));
        }
        v.x *= scale; v.y *= scale; v.z *= scale; v.w *= scale;
        T4[g] = v;
    }
}

__global__ __launch_bounds__(NTHR) void k_encode(const int* __restrict__ tok,
                                                 const float* __restrict__ im,
                                                 float* __restrict__ out) {
    __shared__ float4 T4[HDC_D4];      // 40 KB pre-rotated, pre-scaled row
    __shared__ int    list[CAND];      // 8 KB: matching flat positions
    __shared__ int    nmatch;

    const int t = blockIdx.x;          // token id
    const int y = blockIdx.y;          // position class: i % 8 == y
    const int m = y & 3;               // shared r mod 4 for all rows here

    if (threadIdx.x == 0) nmatch = 0;
    __syncthreads();

    // Phase 1: find positions (candidate i = y + 8*j); token array is L2-hot.
    #pragma unroll
    for (int j = threadIdx.x; j < CAND; j += NTHR) {
        int i = y + PSPLIT * j;
        if (__ldg(&tok[i]) == t) {
            int k = atomicAdd(&nmatch, 1);
            list[k] = i;
        }
    }
    __syncthreads();

    const int n = nmatch;
    if (n == 0) return;

    // Phase 2: stage the pre-rotated, pre-scaled row (blend paid once).
    const float4* sq = reinterpret_cast<const float4*>(im + (size_t)t * HDC_D);
    switch ((4 - m) & 3) {
        case 0: stage<0>(sq, T4, m); break;
        case 1: stage<1>(sq, T4, m); break;
        case 2: stage<2>(sq, T4, m); break;
        default: stage<3>(sq, T4, m); break;
    }
    __syncthreads();

    // Phase 3: emit rows; each is a whole-quad rotation of T.
    // Store address = quad g (sector-aligned); rotation applied on the LDS side.
    for (int p = 0; p < n; ++p) {
        const int bs = list[p];
        const int r  = bs & (HDC_S - 1);        // r mod 4 == m by construction
        const int q0 = (r - m) >> 2;            // whole-quad rotation amount
        float4* dst = reinterpret_cast<float4*>(out + (size_t)bs * HDC_D);

        int qa = (int)threadIdx.x - q0;
        if (qa < 0) qa += HDC_D4;
        for (int g = threadIdx.x; g < HDC_D4; g += NTHR) {
            __stcs(dst + g, T4[qa]);
            qa += NTHR;
            if (qa >= HDC_D4) qa -= HDC_D4;
        }
    }
}

extern "C" void kernel_launch(void* const* d_in, const int* in_sizes, int n_in,
                              void* d_out, int out_size) {
    const int*   tok = (const int*)d_in[0];     // (B, S) int32
    const float* im  = (const float*)d_in[1];   // (V, D) float32
    float*       out = (float*)d_out;           // (B, S, D) float32
    (void)in_sizes; (void)n_in; (void)out_size;

    dim3 grid(HDC_V, PSPLIT);
    k_encode<<<grid, NTHR>>>(tok, im, out);
}

// round 8
// speedup vs baseline: 1.0440x; 1.0397x over previous
#include <cuda_runtime.h>
#include <cstdint>

// ---------------------------------------------------------------------------
// HDCTokenEncoder: out[b,i,d] = item_memory[tok[b,i]][(d - i) mod D] * (1/sqrt(D))
// item_memory entries are exactly +/-1 => row L2 norm == sqrt(D) == 100 exactly,
// so normalization is the constant 0.01f (applied once while staging SMEM).
//
// R8 = R5 emission (proven fastest: load-side rotation, sector-aligned STG.128
// streams) + coalesced candidate scan + merged barrier.
//
// Classes: y in [0,16) -> (c = y>>2, m = y&3). Block (t, y) handles positions
// i in [512c, 512c+512) with i % 4 == m, across all 8 batches (1024 candidates).
// Each int4 of the token array within the chunk contains exactly ONE candidate
// (element m), so the scan is 2 fully-coalesced LDG.128 per thread.
// All rows in a block share m = r mod 4, enabling the pre-rotated staged row
//   T[d] = 0.01 * row[(d - m) mod D]
// so each output row is a whole-quad rotation: load T[(g - q0) mod D4], store
// at quad g (aligned), q0 = (r - m) / 4 in [0, 512).
// ---------------------------------------------------------------------------

#define HDC_D      10000
#define HDC_D4     2500              // D / 4
#define HDC_S      2048              // sequence length (power of two)
#define HDC_B      8
#define HDC_V      256
#define NCLASS     16                // 4 chunks x 4 residues
#define CHUNK      512               // positions per chunk (S / 4)
#define CAND_VEC   1024              // int4 candidates per block (8 b x 128)
#define NTHR       512

template <int OFS>
__device__ __forceinline__ float4 blend(float4 A, float4 B) {
    if (OFS == 0) return A;
    if (OFS == 1) return make_float4(A.y, A.z, A.w, B.x);
    if (OFS == 2) return make_float4(A.z, A.w, B.x, B.y);
    return make_float4(A.w, B.x, B.y, B.z);
}

// Stage T[d] = 0.01 * s[(d - m) mod D]; OFS = (-m) mod 4.
template <int OFS>
__device__ __forceinline__ void stage(const float4* __restrict__ sq,
                                      float4* __restrict__ T4, int m) {
    const float scale = 0.01f;
    #pragma unroll 5
    for (int g = threadIdx.x; g < HDC_D4; g += NTHR) {
        int s0 = 4 * g - m;
        if (s0 < 0) s0 += HDC_D;
        int qa = s0 >> 2;
        float4 v;
        if (OFS == 0) {
            v = __ldg(&sq[qa]);
        } else {
            int qb = qa + 1;
            if (qb == HDC_D4) qb = 0;
            v = blend<OFS>(__ldg(&sq[qa]), __ldg(&sq[qb]));
        }
        v.x *= scale; v.y *= scale; v.z *= scale; v.w *= scale;
        T4[g] = v;
    }
}

__global__ __launch_bounds__(NTHR) void k_encode(const int* __restrict__ tok,
                                                 const float* __restrict__ im,
                                                 float* __restrict__ out) {
    __shared__ float4 T4[HDC_D4];      // 40 KB pre-rotated, pre-scaled row
    __shared__ int    list[CAND_VEC];  // 4 KB: matching flat positions (worst case)
    __shared__ int    nmatch;

    const int t = blockIdx.x;          // token id
    const int y = blockIdx.y;          // class
    const int c = y >> 2;              // chunk index
    const int m = y & 3;               // shared r mod 4 for all rows here

    if (threadIdx.x == 0) nmatch = 0;
    __syncthreads();

    // Phase 1: coalesced scan. int4 vector q (q in [0, 1024)):
    //   b = q >> 7, local = q & 127, i = 512c + 4*local + m, bs = 2048b + i.
    // Exactly one candidate per int4 (element m).
    const int4* tok4 = reinterpret_cast<const int4*>(tok);
    const int vbase = c * (CHUNK / 4);   // c * 128
    #pragma unroll
    for (int q = threadIdx.x; q < CAND_VEC; q += NTHR) {
        int b     = q >> 7;
        int local = q & 127;
        int4 vec  = __ldg(&tok4[b * (HDC_S / 4) + vbase + local]);
        int v = (m < 2) ? (m == 0 ? vec.x : vec.y)
                        : (m == 2 ? vec.z : vec.w);
        if (v == t) {
            int k = atomicAdd(&nmatch, 1);
            list[k] = b * HDC_S + c * CHUNK + 4 * local + m;
        }
    }
    // NOTE: no barrier here — staging is independent of the scan; warps
    // pipeline scan loads under staging loads. One barrier before emission.

    // Phase 2: stage the pre-rotated, pre-scaled row (blend paid once).
    const float4* sq = reinterpret_cast<const float4*>(im + (size_t)t * HDC_D);
    switch ((4 - m) & 3) {
        case 0: stage<0>(sq, T4, m); break;
        case 1: stage<1>(sq, T4, m); break;
        case 2: stage<2>(sq, T4, m); break;
        default: stage<3>(sq, T4, m); break;
    }
    __syncthreads();

    const int n = nmatch;

    // Phase 3: emit rows; each is a whole-quad rotation of T.
    // Store address = quad g (sector-aligned); rotation applied on the LDS side.
    for (int p = 0; p < n; ++p) {
        const int bs = list[p];
        const int r  = bs & (HDC_S - 1);        // r mod 4 == m by construction
        const int q0 = (r - m) >> 2;            // whole-quad rotation amount
        float4* dst = reinterpret_cast<float4*>(out + (size_t)bs * HDC_D);

        int qa = (int)threadIdx.x - q0;
        if (qa < 0) qa += HDC_D4;
        for (int g = threadIdx.x; g < HDC_D4; g += NTHR) {
            __stcs(dst + g, T4[qa]);
            qa += NTHR;
            if (qa >= HDC_D4) qa -= HDC_D4;
        }
    }
}

extern "C" void kernel_launch(void* const* d_in, const int* in_sizes, int n_in,
                              void* d_out, int out_size) {
    const int*   tok = (const int*)d_in[0];     // (B, S) int32
    const float* im  = (const float*)d_in[1];   // (V, D) float32
    float*       out = (float*)d_out;           // (B, S, D) float32
    (void)in_sizes; (void)n_in; (void)out_size;

    dim3 grid(HDC_V, NCLASS);
    k_encode<<<grid, NTHR>>>(tok, im, out);
}

// round 9
// speedup vs baseline: 1.0579x; 1.0133x over previous
#include <cuda_runtime.h>
#include <cstdint>

// ---------------------------------------------------------------------------
// HDCTokenEncoder: out[b,i,d] = item_memory[tok[b,i]][(d - i) mod D] * (1/sqrt(D))
// item_memory entries are exactly +/-1 => row L2 norm == sqrt(D) == 100 exactly,
// so normalization is the constant 0.01f (applied once while staging SMEM).
//
// R9 = R8 (coalesced scan, merged barrier, R5 emission) + register cap.
// R8's pragmas pushed regs 19->46, dropping occupancy to 2 CTAs/SM; the DRAM
// write queue needs ~4 CTAs/SM of store concurrency. __launch_bounds__(512,4)
// restores that; unroll pragmas removed.
//
// Classes: y in [0,16) -> (c = y>>2, m = y&3). Block (t, y) handles positions
// i in [512c, 512c+512) with i % 4 == m, across all 8 batches. Each int4 of
// the token array holds exactly one candidate (element m) -> coalesced scan.
// All rows share m = r mod 4 -> staged row is pre-rotated by m:
//   T[d] = 0.01 * row[(d - m) mod D]
// so each output row is a whole-quad rotation: load T[(g - q0) mod D4], store
// at quad g (sector-aligned STG.128 streams), q0 = (r - m)/4.
// ---------------------------------------------------------------------------

#define HDC_D      10000
#define HDC_D4     2500              // D / 4
#define HDC_S      2048              // sequence length (power of two)
#define HDC_V      256
#define NCLASS     16                // 4 chunks x 4 residues
#define CHUNK      512               // positions per chunk (S / 4)
#define CAND_VEC   1024              // int4 candidates per block (8 batches x 128)
#define NTHR       512

template <int OFS>
__device__ __forceinline__ float4 blend(float4 A, float4 B) {
    if (OFS == 0) return A;
    if (OFS == 1) return make_float4(A.y, A.z, A.w, B.x);
    if (OFS == 2) return make_float4(A.z, A.w, B.x, B.y);
    return make_float4(A.w, B.x, B.y, B.z);
}

// Stage T[d] = 0.01 * s[(d - m) mod D]; OFS = (-m) mod 4.
template <int OFS>
__device__ __forceinline__ void stage(const float4* __restrict__ sq,
                                      float4* __restrict__ T4, int m) {
    const float scale = 0.01f;
    for (int g = threadIdx.x; g < HDC_D4; g += NTHR) {
        int s0 = 4 * g - m;
        if (s0 < 0) s0 += HDC_D;
        int qa = s0 >> 2;
        float4 v;
        if (OFS == 0) {
            v = __ldg(&sq[qa]);
        } else {
            int qb = qa + 1;
            if (qb == HDC_D4) qb = 0;
            v = blend<OFS>(__ldg(&sq[qa]), __ldg(&sq[qb]));
        }
        v.x *= scale; v.y *= scale; v.z *= scale; v.w *= scale;
        T4[g] = v;
    }
}

__global__ __launch_bounds__(NTHR, 4) void k_encode(const int* __restrict__ tok,
                                                    const float* __restrict__ im,
                                                    float* __restrict__ out) {
    __shared__ float4 T4[HDC_D4];      // 40 KB pre-rotated, pre-scaled row
    __shared__ int    list[CAND_VEC];  // 4 KB: matching flat positions
    __shared__ int    nmatch;

    const int t = blockIdx.x;          // token id
    const int y = blockIdx.y;          // class
    const int c = y >> 2;              // chunk index
    const int m = y & 3;               // shared r mod 4 for all rows here

    if (threadIdx.x == 0) nmatch = 0;
    __syncthreads();

    // Phase 1: coalesced scan (2 LDG.128 per thread).
    // int4 vector q in [0,1024): b = q>>7, local = q&127,
    // candidate position i = 512c + 4*local + m, flat bs = 2048b + i.
    const int4* tok4 = reinterpret_cast<const int4*>(tok);
    const int vbase = c * (CHUNK / 4);   // c * 128
    for (int q = threadIdx.x; q < CAND_VEC; q += NTHR) {
        int b     = q >> 7;
        int local = q & 127;
        int4 vec  = __ldg(&tok4[b * (HDC_S / 4) + vbase + local]);
        int v = (m < 2) ? (m == 0 ? vec.x : vec.y)
                        : (m == 2 ? vec.z : vec.w);
        if (v == t) {
            int k = atomicAdd(&nmatch, 1);
            list[k] = b * HDC_S + c * CHUNK + 4 * local + m;
        }
    }
    // No barrier here: staging is independent of the scan; the single barrier
    // below orders both list[] and T4[] before emission.

    // Phase 2: stage the pre-rotated, pre-scaled row (blend paid once).
    const float4* sq = reinterpret_cast<const float4*>(im + (size_t)t * HDC_D);
    switch ((4 - m) & 3) {
        case 0: stage<0>(sq, T4, m); break;
        case 1: stage<1>(sq, T4, m); break;
        case 2: stage<2>(sq, T4, m); break;
        default: stage<3>(sq, T4, m); break;
    }
    __syncthreads();

    const int n = nmatch;

    // Phase 3: emit rows; each is a whole-quad rotation of T.
    // Store address = quad g (sector-aligned); rotation applied on the LDS side.
    for (int p = 0; p < n; ++p) {
        const int bs = list[p];
        const int r  = bs & (HDC_S - 1);        // r mod 4 == m by construction
        const int q0 = (r - m) >> 2;            // whole-quad rotation amount
        float4* dst = reinterpret_cast<float4*>(out + (size_t)bs * HDC_D);

        int qa = (int)threadIdx.x - q0;
        if (qa < 0) qa += HDC_D4;
        for (int g = threadIdx.x; g < HDC_D4; g += NTHR) {
            __stcs(dst + g, T4[qa]);
            qa += NTHR;
            if (qa >= HDC_D4) qa -= HDC_D4;
        }
    }
}

extern "C" void kernel_launch(void* const* d_in, const int* in_sizes, int n_in,
                              void* d_out, int out_size) {
    const int*   tok = (const int*)d_in[0];     // (B, S) int32
    const float* im  = (const float*)d_in[1];   // (V, D) float32
    float*       out = (float*)d_out;           // (B, S, D) float32
    (void)in_sizes; (void)n_in; (void)out_size;

    dim3 grid(HDC_V, NCLASS);
    k_encode<<<grid, NTHR>>>(tok, im, out);
}

// round 10
// speedup vs baseline: 1.0623x; 1.0041x over previous
#include <cuda_runtime.h>
#include <cstdint>

// ---------------------------------------------------------------------------
// HDCTokenEncoder: out[b,i,d] = item_memory[tok[b,i]][(d - i) mod D] * (1/sqrt(D))
// item_memory entries are exactly +/-1 => row L2 norm == sqrt(D) == 100 exactly,
// so normalization is the constant 0.01f (applied once while staging SMEM).
//
// R10 = R9 + paired-row emission. The single-row loop had a thin serial
// LDS->STG chain (~1-2 stores in flight/warp) leaving the DRAM write queue
// underfilled (stuck ~76%). Emitting TWO rows per loop gives two independent
// LDS->STG chains with BOTH stores at the same aligned quad g of their rows
// (no R6-style misalignment), ~2x in-flight stores.
//
// Classes: y in [0,16) -> (c = y>>2, m = y&3). Block (t, y) handles positions
// i in [512c, 512c+512) with i % 4 == m, across all 8 batches. Each int4 of
// the token array holds exactly one candidate (element m) -> coalesced scan.
// All rows share m = r mod 4 -> staged row is pre-rotated by m:
//   T[d] = 0.01 * row[(d - m) mod D]
// so each output row is a whole-quad rotation: load T[(g - q0) mod D4], store
// at quad g (sector-aligned STG.128 streams), q0 = (r - m)/4.
// ---------------------------------------------------------------------------

#define HDC_D      10000
#define HDC_D4     2500              // D / 4
#define HDC_S      2048              // sequence length (power of two)
#define HDC_V      256
#define NCLASS     16                // 4 chunks x 4 residues
#define CHUNK      512               // positions per chunk (S / 4)
#define CAND_VEC   1024              // int4 candidates per block (8 batches x 128)
#define NTHR       512

template <int OFS>
__device__ __forceinline__ float4 blend(float4 A, float4 B) {
    if (OFS == 0) return A;
    if (OFS == 1) return make_float4(A.y, A.z, A.w, B.x);
    if (OFS == 2) return make_float4(A.z, A.w, B.x, B.y);
    return make_float4(A.w, B.x, B.y, B.z);
}

// Stage T[d] = 0.01 * s[(d - m) mod D]; OFS = (-m) mod 4.
template <int OFS>
__device__ __forceinline__ void stage(const float4* __restrict__ sq,
                                      float4* __restrict__ T4, int m) {
    const float scale = 0.01f;
    for (int g = threadIdx.x; g < HDC_D4; g += NTHR) {
        int s0 = 4 * g - m;
        if (s0 < 0) s0 += HDC_D;
        int qa = s0 >> 2;
        float4 v;
        if (OFS == 0) {
            v = __ldg(&sq[qa]);
        } else {
            int qb = qa + 1;
            if (qb == HDC_D4) qb = 0;
            v = blend<OFS>(__ldg(&sq[qa]), __ldg(&sq[qb]));
        }
        v.x *= scale; v.y *= scale; v.z *= scale; v.w *= scale;
        T4[g] = v;
    }
}

// One row: out quad g <- T quad (g - q0) mod D4.
__device__ __forceinline__ void emit1(const float4* __restrict__ T4,
                                      float4* __restrict__ dst, int q0) {
    int qa = (int)threadIdx.x - q0;
    if (qa < 0) qa += HDC_D4;
    for (int g = threadIdx.x; g < HDC_D4; g += NTHR) {
        __stcs(dst + g, T4[qa]);
        qa += NTHR;
        if (qa >= HDC_D4) qa -= HDC_D4;
    }
}

// Two rows in lockstep: independent LDS->STG chains, both stores aligned at g.
__device__ __forceinline__ void emit2(const float4* __restrict__ T4,
                                      float4* __restrict__ d0,
                                      float4* __restrict__ d1,
                                      int q00, int q01) {
    int qa0 = (int)threadIdx.x - q00;
    if (qa0 < 0) qa0 += HDC_D4;
    int qa1 = (int)threadIdx.x - q01;
    if (qa1 < 0) qa1 += HDC_D4;
    for (int g = threadIdx.x; g < HDC_D4; g += NTHR) {
        float4 v0 = T4[qa0];
        float4 v1 = T4[qa1];
        __stcs(d0 + g, v0);
        __stcs(d1 + g, v1);
        qa0 += NTHR; if (qa0 >= HDC_D4) qa0 -= HDC_D4;
        qa1 += NTHR; if (qa1 >= HDC_D4) qa1 -= HDC_D4;
    }
}

__global__ __launch_bounds__(NTHR, 4) void k_encode(const int* __restrict__ tok,
                                                    const float* __restrict__ im,
                                                    float* __restrict__ out) {
    __shared__ float4 T4[HDC_D4];      // 40 KB pre-rotated, pre-scaled row
    __shared__ int    list[CAND_VEC];  // 4 KB: matching flat positions
    __shared__ int    nmatch;

    const int t = blockIdx.x;          // token id
    const int y = blockIdx.y;          // class
    const int c = y >> 2;              // chunk index
    const int m = y & 3;               // shared r mod 4 for all rows here

    if (threadIdx.x == 0) nmatch = 0;
    __syncthreads();

    // Phase 1: coalesced scan (2 LDG.128 per thread).
    // int4 vector q in [0,1024): b = q>>7, local = q&127,
    // candidate position i = 512c + 4*local + m, flat bs = 2048b + i.
    const int4* tok4 = reinterpret_cast<const int4*>(tok);
    const int vbase = c * (CHUNK / 4);   // c * 128
    for (int q = threadIdx.x; q < CAND_VEC; q += NTHR) {
        int b     = q >> 7;
        int local = q & 127;
        int4 vec  = __ldg(&tok4[b * (HDC_S / 4) + vbase + local]);
        int v = (m < 2) ? (m == 0 ? vec.x : vec.y)
                        : (m == 2 ? vec.z : vec.w);
        if (v == t) {
            int k = atomicAdd(&nmatch, 1);
            list[k] = b * HDC_S + c * CHUNK + 4 * local + m;
        }
    }
    // No barrier here: staging is independent of the scan; the single barrier
    // below orders both list[] and T4[] before emission.

    // Phase 2: stage the pre-rotated, pre-scaled row (blend paid once).
    const float4* sq = reinterpret_cast<const float4*>(im + (size_t)t * HDC_D);
    switch ((4 - m) & 3) {
        case 0: stage<0>(sq, T4, m); break;
        case 1: stage<1>(sq, T4, m); break;
        case 2: stage<2>(sq, T4, m); break;
        default: stage<3>(sq, T4, m); break;
    }
    __syncthreads();

    const int n = nmatch;

    // Phase 3: emit rows in pairs (two aligned store streams in flight).
    int p = 0;
    for (; p + 2 <= n; p += 2) {
        const int bs0 = list[p];
        const int bs1 = list[p + 1];
        const int q00 = ((bs0 & (HDC_S - 1)) - m) >> 2;
        const int q01 = ((bs1 & (HDC_S - 1)) - m) >> 2;
        emit2(T4,
              reinterpret_cast<float4*>(out + (size_t)bs0 * HDC_D),
              reinterpret_cast<float4*>(out + (size_t)bs1 * HDC_D),
              q00, q01);
    }
    if (p < n) {
        const int bs = list[p];
        const int q0 = ((bs & (HDC_S - 1)) - m) >> 2;
        emit1(T4, reinterpret_cast<float4*>(out + (size_t)bs * HDC_D), q0);
    }
}

extern "C" void kernel_launch(void* const* d_in, const int* in_sizes, int n_in,
                              void* d_out, int out_size) {
    const int*   tok = (const int*)d_in[0];     // (B, S) int32
    const float* im  = (const float*)d_in[1];   // (V, D) float32
    float*       out = (float*)d_out;           // (B, S, D) float32
    (void)in_sizes; (void)n_in; (void)out_size;

    dim3 grid(HDC_V, NCLASS);
    k_encode<<<grid, NTHR>>>(tok, im, out);
}